// round 7
// baseline (speedup 1.0000x reference)
#include <cuda_runtime.h>
#include <cuda_bf16.h>

// Fixed problem shapes
#define NBOX 256
#define CPL  256
#define UH   200
#define UW   304
#define H1   100
#define W1   152
#define H2   50
#define W2   76

#define TPB 392   // R3 mapping: cell = tid % 49, cl = tid / 49 (empirically best)

// Compute tap list for (lvl, axis, cell p). Returns count; fills ci/cw, mn/mx.
__device__ __forceinline__ int make_taps(int lvl, int axis, int p,
                                         float b1, float bt,
                                         int* ci, float* cw, int& mn, int& mx)
{
    const int updim = axis ? UH : UW;
    int e = 0; mn = 1 << 30; mx = -1;
    if (lvl == 0) {
        #pragma unroll
        for (int s = 0; s < 2; s++) {
            float T  = b1 + ((float)p + 0.25f + 0.5f * (float)s) * bt;
            float Tc = fminf(fmaxf(T, 0.0f), (float)(updim - 1));
            int   i0 = (int)Tc;
            int   i1 = min(i0 + 1, updim - 1);
            float f  = Tc - (float)i0;
            ci[e] = i0; cw[e] = 0.5f * (1.0f - f); e++;
            ci[e] = i1; cw[e] = 0.5f * f;          e++;
            mn = min(mn, i0); mx = max(mx, i1);
        }
    } else {
        const float inv  = (lvl == 1) ? 0.5f : 0.25f;
        const int   cdim = axis ? ((lvl == 1) ? H1 : H2)
                                : ((lvl == 1) ? W1 : W2);
        #pragma unroll
        for (int s = 0; s < 2; s++) {
            float T  = b1 + ((float)p + 0.25f + 0.5f * (float)s) * bt;
            float Tc = fminf(fmaxf(T, 0.0f), (float)(updim - 1));
            int   u0 = (int)Tc;
            int   u1 = min(u0 + 1, updim - 1);
            float fu = Tc - (float)u0;
            #pragma unroll
            for (int b = 0; b < 2; b++) {
                int   u  = b ? u1 : u0;
                float wu = b ? (0.5f * fu) : (0.5f * (1.0f - fu));
                float g  = ((float)u + 0.5f) * inv - 0.5f;
                g = fminf(fmaxf(g, 0.0f), (float)(cdim - 1));
                int   c0 = (int)g;
                int   c1 = min(c0 + 1, cdim - 1);
                float fc = g - (float)c0;
                ci[e] = c0; cw[e] = wu * (1.0f - fc); e++;
                ci[e] = c1; cw[e] = wu * fc;          e++;
                mn = min(mn, c0); mx = max(mx, c1);
            }
        }
    }
    return e;
}

// Fully-unrolled channel-loop body: R rows x XF4 float4 columns.
template<int R, int XF4>
__device__ __forceinline__ void roi_body(
    const float* __restrict__ base, int W_, int cstr,
    const float* __restrict__ sxw, const float* __restrict__ syw,
    int xb, int yb, int cl, float* __restrict__ op)
{
    float xw[4 * XF4];
    #pragma unroll
    for (int j = 0; j < 4 * XF4; j++) xw[j] = sxw[j];
    float yw[R];
    #pragma unroll
    for (int r = 0; r < R; r++) yw[r] = syw[r];

    const float* p0 = base + yb * W_ + xb;
    for (int c = cl; c < CPL; c += 8) {        // compiler-chosen unroll (R3 behavior)
        const float* pl = p0 + c * cstr;
        float acc = 0.0f;
        #pragma unroll
        for (int r = 0; r < R; r++) {
            const float4* row = (const float4*)(pl + r * W_);
            float rs = 0.0f;
            #pragma unroll
            for (int j = 0; j < XF4; j++) {
                float4 v = __ldg(row + j);
                rs += xw[4 * j + 0] * v.x + xw[4 * j + 1] * v.y
                    + xw[4 * j + 2] * v.z + xw[4 * j + 3] * v.w;
            }
            acc = fmaf(yw[r], rs, acc);
        }
        op[c * 49] = acc;
    }
}

__global__ void __launch_bounds__(TPB)
fused_roialign_kernel(const float* __restrict__ feat0,
                      const float* __restrict__ feat1,
                      const float* __restrict__ feat2,
                      const float* __restrict__ boxes,
                      float* __restrict__ out)
{
    const int n   = blockIdx.x;
    const int lvl = blockIdx.y;
    const int tid = threadIdx.x;

    __shared__ float s_xw[7][12];
    __shared__ int   s_xb[7];
    __shared__ float s_yw[7][7];
    __shared__ int   s_yb[7];
    __shared__ int   s_span[7];
    __shared__ int   s_rN;

    const int dimx = (lvl == 0) ? UW : ((lvl == 1) ? W1 : W2);
    const int dimy = (lvl == 0) ? UH : ((lvl == 1) ? H1 : H2);
    const int XW   = (lvl == 0) ? 12 : 8;   // x window width (3 or 2 float4s)

    // ---- phase A: x windows + y spans --------------------------------------
    if (tid < 14) {
        const int axis = tid / 7;
        const int p    = tid % 7;
        float b1 = boxes[n * 4 + axis]     * 0.25f;
        float b2 = boxes[n * 4 + 2 + axis] * 0.25f;
        float bt = fmaxf(b2 - b1, 1.0f) * (1.0f / 7.0f);

        int ci[8]; float cw[8]; int mn, mx;
        int ntap = make_taps(lvl, axis, p, b1, bt, ci, cw, mn, mx);

        if (axis == 0) {
            int xb = min(mn & ~3, dimx - XW);
            float w[12];
            #pragma unroll
            for (int k = 0; k < 12; k++) w[k] = 0.0f;
            for (int k = 0; k < ntap; k++) {
                int off = min(max(ci[k] - xb, 0), XW - 1);
                w[off] += cw[k];
            }
            s_xb[p] = xb;
            #pragma unroll
            for (int k = 0; k < 12; k++) s_xw[p][k] = w[k];
        } else {
            s_span[p] = mx - mn + 1;
        }
    }
    __syncthreads();
    if (tid == 0) {
        int r = 1;
        #pragma unroll
        for (int k = 0; k < 7; k++) r = max(r, s_span[k]);
        s_rN = r;
    }
    __syncthreads();
    const int rN = s_rN;

    // ---- phase B: y windows sized to uniform rN ----------------------------
    if (tid < 7) {
        const int p = tid;
        float b1 = boxes[n * 4 + 1] * 0.25f;
        float b2 = boxes[n * 4 + 3] * 0.25f;
        float bt = fmaxf(b2 - b1, 1.0f) * (1.0f / 7.0f);

        int ci[8]; float cw[8]; int mn, mx;
        int ntap = make_taps(lvl, 1, p, b1, bt, ci, cw, mn, mx);

        int yb = min(mn, dimy - rN);
        float w[7];
        #pragma unroll
        for (int k = 0; k < 7; k++) w[k] = 0.0f;
        for (int k = 0; k < ntap; k++) {
            int off = min(max(ci[k] - yb, 0), rN - 1);
            w[off] += cw[k];
        }
        s_yb[p] = yb;
        #pragma unroll
        for (int k = 0; k < 7; k++) s_yw[p][k] = w[k];
    }
    __syncthreads();

    // ---- main loop ---------------------------------------------------------
    const int cell = tid % 49;
    const int cl   = tid / 49;
    const int oh   = cell / 7;
    const int ow   = cell % 7;
    float* op = out + ((size_t)(n * 768 + lvl * CPL) * 49) + cell;

    if (lvl == 0) {
        switch (rN) {
            case 1: roi_body<1,3>(feat0, UW, UH*UW, s_xw[ow], s_yw[oh], s_xb[ow], s_yb[oh], cl, op); break;
            case 2: roi_body<2,3>(feat0, UW, UH*UW, s_xw[ow], s_yw[oh], s_xb[ow], s_yb[oh], cl, op); break;
            case 3: roi_body<3,3>(feat0, UW, UH*UW, s_xw[ow], s_yw[oh], s_xb[ow], s_yb[oh], cl, op); break;
            case 4: roi_body<4,3>(feat0, UW, UH*UW, s_xw[ow], s_yw[oh], s_xb[ow], s_yb[oh], cl, op); break;
            case 5: roi_body<5,3>(feat0, UW, UH*UW, s_xw[ow], s_yw[oh], s_xb[ow], s_yb[oh], cl, op); break;
            case 6: roi_body<6,3>(feat0, UW, UH*UW, s_xw[ow], s_yw[oh], s_xb[ow], s_yb[oh], cl, op); break;
            default: roi_body<7,3>(feat0, UW, UH*UW, s_xw[ow], s_yw[oh], s_xb[ow], s_yb[oh], cl, op); break;
        }
    } else {
        const float* base = (lvl == 1) ? feat1 : feat2;
        const int W_   = (lvl == 1) ? W1 : W2;
        const int cstr = (lvl == 1) ? (H1 * W1) : (H2 * W2);
        switch (rN) {
            case 1: roi_body<1,2>(base, W_, cstr, s_xw[ow], s_yw[oh], s_xb[ow], s_yb[oh], cl, op); break;
            case 2: roi_body<2,2>(base, W_, cstr, s_xw[ow], s_yw[oh], s_xb[ow], s_yb[oh], cl, op); break;
            case 3: roi_body<3,2>(base, W_, cstr, s_xw[ow], s_yw[oh], s_xb[ow], s_yb[oh], cl, op); break;
            case 4: roi_body<4,2>(base, W_, cstr, s_xw[ow], s_yw[oh], s_xb[ow], s_yb[oh], cl, op); break;
            default: roi_body<5,2>(base, W_, cstr, s_xw[ow], s_yw[oh], s_xb[ow], s_yb[oh], cl, op); break;
        }
    }
}

extern "C" void kernel_launch(void* const* d_in, const int* in_sizes, int n_in,
                              void* d_out, int out_size) {
    const float* feat0 = (const float*)d_in[0];
    const float* feat1 = (const float*)d_in[1];
    const float* feat2 = (const float*)d_in[2];
    const float* boxes = (const float*)d_in[3];
    float* out = (float*)d_out;

    dim3 grid(NBOX, 3);
    fused_roialign_kernel<<<grid, TPB>>>(feat0, feat1, feat2, boxes, out);
}

// round 10
// speedup vs baseline: 1.8834x; 1.8834x over previous
#include <cuda_runtime.h>
#include <cuda_bf16.h>

// Fixed problem shapes
#define NBOX 256
#define CPL  256
#define UH   200
#define UW   304
#define H1   100
#define W1   152
#define H2   50
#define W2   76

#define TPB 392   // R3 mapping: cell = tid % 49, cl = tid / 49

// Coarse-level y tap builder (axis = y). Fills ci/cw, returns count; sets mn.
__device__ __forceinline__ int coarse_taps_y(int lvl, int p, float b1, float bt,
                                             int* ci, float* cw, int& mn)
{
    const float inv  = (lvl == 1) ? 0.5f : 0.25f;
    const int   cdim = (lvl == 1) ? H1 : H2;
    int e = 0; mn = 1 << 30;
    #pragma unroll
    for (int s = 0; s < 2; s++) {
        float T  = b1 + ((float)p + 0.25f + 0.5f * (float)s) * bt;
        float Tc = fminf(fmaxf(T, 0.0f), (float)(UH - 1));
        int   u0 = (int)Tc;
        int   u1 = min(u0 + 1, UH - 1);
        float fu = Tc - (float)u0;
        #pragma unroll
        for (int b = 0; b < 2; b++) {
            int   u  = b ? u1 : u0;
            float wu = b ? (0.5f * fu) : (0.5f * (1.0f - fu));
            float g  = ((float)u + 0.5f) * inv - 0.5f;
            g = fminf(fmaxf(g, 0.0f), (float)(cdim - 1));
            int   c0 = (int)g;
            int   c1 = min(c0 + 1, cdim - 1);
            float fc = g - (float)c0;
            ci[e] = c0; cw[e] = wu * (1.0f - fc); e++;
            ci[e] = c1; cw[e] = wu * fc;          e++;
            mn = min(mn, c0);
        }
    }
    return e;
}

// Coarse-level channel-loop body: R rows x 2 float4 columns, fully unrolled rows.
template<int R>
__device__ __forceinline__ void coarse_body(
    const float* __restrict__ base, int W_, int cstr,
    const float* __restrict__ sxw, const float* __restrict__ syw,
    int xb, int yb, int cl, float* __restrict__ op)
{
    float xw[8];
    #pragma unroll
    for (int j = 0; j < 8; j++) xw[j] = sxw[j];
    float yw[R];
    #pragma unroll
    for (int r = 0; r < R; r++) yw[r] = syw[r];

    const float* p0 = base + yb * W_ + xb;
    for (int c = cl; c < CPL; c += 8) {     // auto-unrolled (R3 behavior)
        const float* pl = p0 + c * cstr;
        float acc = 0.0f;
        #pragma unroll
        for (int r = 0; r < R; r++) {
            const float4* row = (const float4*)(pl + r * W_);
            float4 a = __ldg(row);
            float4 b = __ldg(row + 1);
            float rs = xw[0] * a.x + xw[1] * a.y + xw[2] * a.z + xw[3] * a.w
                     + xw[4] * b.x + xw[5] * b.y + xw[6] * b.z + xw[7] * b.w;
            acc = fmaf(yw[r], rs, acc);
        }
        op[c * 49] = acc;
    }
}

__global__ void __launch_bounds__(TPB)
fused_roialign_kernel(const float* __restrict__ feat0,
                      const float* __restrict__ feat1,
                      const float* __restrict__ feat2,
                      const float* __restrict__ boxes,
                      float* __restrict__ out)
{
    const int n   = blockIdx.x;
    const int lvl = blockIdx.y;
    const int tid = threadIdx.x;

    // Level-0 tap tables: [axis][pos][tap]
    __shared__ float s_w0[2][7][4];
    __shared__ int   s_i0[2][7][4];
    // Coarse-level windows
    __shared__ float s_xw[7][8];
    __shared__ int   s_xb[7];
    __shared__ float s_yw[7][5];
    __shared__ int   s_yb[7];
    __shared__ int   s_ymn[7], s_ymx[7];
    __shared__ int   s_rN;

    // ---- phase A: lvl0 scalar tables, coarse x windows, coarse y spans -----
    if (tid < 14) {
        const int axis = tid / 7;          // 0 = x, 1 = y
        const int p    = tid % 7;
        float b1 = boxes[n * 4 + axis]     * 0.25f;
        float b2 = boxes[n * 4 + 2 + axis] * 0.25f;
        float rb = fmaxf(b2 - b1, 1.0f);
        float bt = rb * (1.0f / 7.0f);
        const int updim = axis ? UH : UW;

        if (lvl == 0) {
            #pragma unroll
            for (int s = 0; s < 2; s++) {
                float T  = b1 + ((float)p + 0.25f + 0.5f * (float)s) * bt;
                float Tc = fminf(fmaxf(T, 0.0f), (float)(updim - 1));
                int   i0 = (int)Tc;
                int   i1 = min(i0 + 1, updim - 1);
                float f  = Tc - (float)i0;
                s_i0[axis][p][2 * s + 0] = i0;
                s_i0[axis][p][2 * s + 1] = i1;
                s_w0[axis][p][2 * s + 0] = 0.5f * (1.0f - f);
                s_w0[axis][p][2 * s + 1] = 0.5f * f;
            }
        } else {
            const float inv  = (lvl == 1) ? 0.5f : 0.25f;
            const int   cdim = axis ? ((lvl == 1) ? H1 : H2)
                                    : ((lvl == 1) ? W1 : W2);
            int   ci[8];
            float cw[8];
            int   mn = 1 << 30, mx = -1;
            int   e  = 0;
            #pragma unroll
            for (int s = 0; s < 2; s++) {
                float T  = b1 + ((float)p + 0.25f + 0.5f * (float)s) * bt;
                float Tc = fminf(fmaxf(T, 0.0f), (float)(updim - 1));
                int   u0 = (int)Tc;
                int   u1 = min(u0 + 1, updim - 1);
                float fu = Tc - (float)u0;
                #pragma unroll
                for (int b = 0; b < 2; b++) {
                    int   u  = b ? u1 : u0;
                    float wu = b ? (0.5f * fu) : (0.5f * (1.0f - fu));
                    float g  = ((float)u + 0.5f) * inv - 0.5f;
                    g = fminf(fmaxf(g, 0.0f), (float)(cdim - 1));
                    int   c0 = (int)g;
                    int   c1 = min(c0 + 1, cdim - 1);
                    float fc = g - (float)c0;
                    ci[e] = c0; cw[e] = wu * (1.0f - fc); e++;
                    ci[e] = c1; cw[e] = wu * fc;          e++;
                    mn = min(mn, c0); mx = max(mx, c1);
                }
            }
            if (axis == 0) {
                int xb = min(mn & ~3, cdim - 8);   // float4-aligned window of 8
                float w[8] = {0, 0, 0, 0, 0, 0, 0, 0};
                #pragma unroll
                for (int k = 0; k < 8; k++) {
                    int off = min(max(ci[k] - xb, 0), 7);
                    w[off] += cw[k];
                }
                s_xb[p] = xb;
                #pragma unroll
                for (int k = 0; k < 8; k++) s_xw[p][k] = w[k];
            } else {
                s_ymn[p] = mn;
                s_ymx[p] = mx;
            }
        }
    }
    __syncthreads();

    if (lvl != 0 && tid == 0) {
        int r = 1;
        #pragma unroll
        for (int k = 0; k < 7; k++) r = max(r, s_ymx[k] - s_ymn[k] + 1);
        s_rN = r;
    }
    __syncthreads();

    // ---- phase B: coarse y windows anchored with the known rN --------------
    if (lvl != 0 && tid < 7) {
        const int p = tid;
        const int cdim = (lvl == 1) ? H1 : H2;
        const int rN = s_rN;
        float b1 = boxes[n * 4 + 1] * 0.25f;
        float b2 = boxes[n * 4 + 3] * 0.25f;
        float bt = fmaxf(b2 - b1, 1.0f) * (1.0f / 7.0f);

        int ci[8]; float cw[8]; int mn;
        int ntap = coarse_taps_y(lvl, p, b1, bt, ci, cw, mn);

        int yb = min(mn, cdim - rN);       // anchored with rN: offsets <= rN-1
        float w[5] = {0, 0, 0, 0, 0};
        for (int k = 0; k < ntap; k++) {
            int off = min(max(ci[k] - yb, 0), rN - 1);
            w[off] += cw[k];
        }
        s_yb[p] = yb;
        #pragma unroll
        for (int k = 0; k < 5; k++) s_yw[p][k] = w[k];
    }
    __syncthreads();

    // ---- main loop ---------------------------------------------------------
    const int cell = tid % 49;
    const int cl   = tid / 49;
    const int oh   = cell / 7;
    const int ow   = cell % 7;
    float* op = out + ((size_t)(n * 768 + lvl * CPL) * 49) + cell;

    if (lvl == 0) {
        int   xi0 = s_i0[0][ow][0], xi1 = s_i0[0][ow][1], xi2 = s_i0[0][ow][2], xi3 = s_i0[0][ow][3];
        float xw0 = s_w0[0][ow][0], xw1 = s_w0[0][ow][1], xw2 = s_w0[0][ow][2], xw3 = s_w0[0][ow][3];
        int   ro0 = s_i0[1][oh][0] * UW, ro1 = s_i0[1][oh][1] * UW,
              ro2 = s_i0[1][oh][2] * UW, ro3 = s_i0[1][oh][3] * UW;
        float yw0 = s_w0[1][oh][0], yw1 = s_w0[1][oh][1], yw2 = s_w0[1][oh][2], yw3 = s_w0[1][oh][3];

        for (int c = cl; c < CPL; c += 8) {
            const float* pl = feat0 + c * (UH * UW);
            const float* r0 = pl + ro0;
            const float* r1 = pl + ro1;
            const float* r2 = pl + ro2;
            const float* r3 = pl + ro3;
            float s0 = xw0 * __ldg(r0 + xi0) + xw1 * __ldg(r0 + xi1)
                     + xw2 * __ldg(r0 + xi2) + xw3 * __ldg(r0 + xi3);
            float s1 = xw0 * __ldg(r1 + xi0) + xw1 * __ldg(r1 + xi1)
                     + xw2 * __ldg(r1 + xi2) + xw3 * __ldg(r1 + xi3);
            float s2 = xw0 * __ldg(r2 + xi0) + xw1 * __ldg(r2 + xi1)
                     + xw2 * __ldg(r2 + xi2) + xw3 * __ldg(r2 + xi3);
            float s3 = xw0 * __ldg(r3 + xi0) + xw1 * __ldg(r3 + xi1)
                     + xw2 * __ldg(r3 + xi2) + xw3 * __ldg(r3 + xi3);
            op[c * 49] = yw0 * s0 + yw1 * s1 + yw2 * s2 + yw3 * s3;
        }
    } else {
        const float* base = (lvl == 1) ? feat1 : feat2;
        const int W_   = (lvl == 1) ? W1 : W2;
        const int cstr = (lvl == 1) ? (H1 * W1) : (H2 * W2);
        const int rN   = s_rN;
        const int xb = s_xb[ow];
        const int yb = s_yb[oh];

        if (lvl == 1) {
            switch (rN) {
                case 1: coarse_body<1>(base, W_, cstr, s_xw[ow], s_yw[oh], xb, yb, cl, op); break;
                case 2: coarse_body<2>(base, W_, cstr, s_xw[ow], s_yw[oh], xb, yb, cl, op); break;
                case 3: coarse_body<3>(base, W_, cstr, s_xw[ow], s_yw[oh], xb, yb, cl, op); break;
                case 4: coarse_body<4>(base, W_, cstr, s_xw[ow], s_yw[oh], xb, yb, cl, op); break;
                default: coarse_body<5>(base, W_, cstr, s_xw[ow], s_yw[oh], xb, yb, cl, op); break;
            }
        } else {
            switch (rN) {
                case 1: coarse_body<1>(base, W_, cstr, s_xw[ow], s_yw[oh], xb, yb, cl, op); break;
                case 2: coarse_body<2>(base, W_, cstr, s_xw[ow], s_yw[oh], xb, yb, cl, op); break;
                case 3: coarse_body<3>(base, W_, cstr, s_xw[ow], s_yw[oh], xb, yb, cl, op); break;
                default: coarse_body<4>(base, W_, cstr, s_xw[ow], s_yw[oh], xb, yb, cl, op); break;
            }
        }
    }
}

extern "C" void kernel_launch(void* const* d_in, const int* in_sizes, int n_in,
                              void* d_out, int out_size) {
    const float* feat0 = (const float*)d_in[0];
    const float* feat1 = (const float*)d_in[1];
    const float* feat2 = (const float*)d_in[2];
    const float* boxes = (const float*)d_in[3];
    float* out = (float*)d_out;

    dim3 grid(NBOX, 3);
    fused_roialign_kernel<<<grid, TPB>>>(feat0, feat1, feat2, boxes, out);
}